// round 6
// baseline (speedup 1.0000x reference)
#include <cuda_runtime.h>
#include <cstdint>

#define T_STEPS 1000
#define BATCH   2048
#define FEAT    40
#define H1      8
#define H2      6
#define G1      32
#define G2      24

typedef unsigned long long u64;

// gate scratch: [elem][t][gate] fp32, pre-scaled by activation input scale. 262 MB.
__device__ float g_xg[(size_t)BATCH * T_STEPS * G1];

// ---------------- f32x2 helpers ----------------
__device__ __forceinline__ u64 pack2(float x, float y) {
    u64 r; asm("mov.b64 %0, {%1, %2};" : "=l"(r) : "f"(x), "f"(y)); return r;
}
__device__ __forceinline__ void unpack2(u64 v, float& x, float& y) {
    asm("mov.b64 {%0, %1}, %2;" : "=f"(x), "=f"(y) : "l"(v));
}
__device__ __forceinline__ u64 fma2(u64 a, u64 b, u64 c) {
    u64 d; asm("fma.rn.f32x2 %0, %1, %2, %3;" : "=l"(d) : "l"(a), "l"(b), "l"(c)); return d;
}
__device__ __forceinline__ u64 mul2(u64 a, u64 b) {
    u64 d; asm("mul.rn.f32x2 %0, %1, %2;" : "=l"(d) : "l"(a), "l"(b)); return d;
}
__device__ __forceinline__ u64 add2(u64 a, u64 b) {
    u64 d; asm("add.rn.f32x2 %0, %1, %2;" : "=l"(d) : "l"(a), "l"(b)); return d;
}
__device__ __forceinline__ u64 scale2(u64 v, float s) {
    float a, b; unpack2(v, a, b); return pack2(a * s, b * s);
}
__device__ __forceinline__ float hadd2(u64 v) {
    float a, b; unpack2(v, a, b); return a + b;
}
__device__ __forceinline__ float tanha(float x) {
    float r; asm("tanh.approx.f32 %0, %1;" : "=f"(r) : "f"(x)); return r;
}
__device__ __forceinline__ float shflf(float v, int src) {
    return __shfl_sync(0xffffffffu, v, src & 31);
}

// ============================================================================
// Kernel 1: projection. G=2 register blocking: lane holds gates (l, l+16);
// half-warps cover two t-rows per pass, so each x LDS.128 feeds 4 outputs.
// Output gates are pre-scaled by the activation input scale (cm).
// ============================================================================
#define PTILE 40          // t-rows per shared tile
#define PBLK  128

__global__ void __launch_bounds__(PBLK)
proj_kernel(const float* __restrict__ x,
            const float* __restrict__ W,
            const float* __restrict__ bi,
            const float* __restrict__ bh) {
    __shared__ __align__(16) float sx[PTILE][FEAT];   // rows 160B apart (8-bank shift)

    int tid  = threadIdx.x;
    int lane = tid & 31, warp = tid >> 5;
    int l    = lane & 15;       // gate base (0..15)
    int h    = lane >> 4;       // row half (0/1)
    int e    = blockIdx.x >> 1;
    int half = blockIdx.x & 1;

    int gA = l, gB = l + 16;
    float cmA = 0.5f;                      // gates 0..15 = i/f (sigmoid)
    float cmB = (l < 8) ? 1.0f : 0.5f;     // 16..23 = cell (tanh), 24..31 = o (sigmoid)

    u64 wA[FEAT / 2], wB[FEAT / 2];
    {
        const u64* wra = reinterpret_cast<const u64*>(W + gA * FEAT);
        const u64* wrb = reinterpret_cast<const u64*>(W + gB * FEAT);
#pragma unroll
        for (int p = 0; p < FEAT / 2; p++) {
            wA[p] = scale2(wra[p], cmA);
            wB[p] = scale2(wrb[p], cmB);
        }
    }
    float bA = cmA * (bi[gA] + bh[gA]);
    float bB = cmB * (bi[gB] + bh[gB]);

    const float4* xg = reinterpret_cast<const float4*>(x + (size_t)e * T_STEPS * FEAT);
    float* og = g_xg + (size_t)e * T_STEPS * G1;

    int tile0 = half ? 13 : 0;
    int tile1 = half ? 25 : 13;

#pragma unroll 1
    for (int tile = tile0; tile < tile1; tile++) {
        __syncthreads();
#pragma unroll
        for (int i = 0; i < 4; i++) {
            int s = tid + PBLK * i;
            if (s < PTILE * FEAT / 4)
                reinterpret_cast<float4*>(&sx[0][0])[s] = xg[tile * (PTILE * FEAT / 4) + s];
        }
        __syncthreads();

#pragma unroll
        for (int p = 0; p < 5; p++) {
            int r = warp * 10 + 2 * p + h;
            const ulonglong2* xr = reinterpret_cast<const ulonglong2*>(&sx[r][0]);
            u64 a0 = pack2(bA, 0.f), a1 = 0ull;
            u64 b0 = pack2(bB, 0.f), b1 = 0ull;
#pragma unroll
            for (int q = 0; q < FEAT / 4; q++) {
                ulonglong2 v = xr[q];
                a0 = fma2(wA[2 * q],     v.x, a0);
                a1 = fma2(wA[2 * q + 1], v.y, a1);
                b0 = fma2(wB[2 * q],     v.x, b0);
                b1 = fma2(wB[2 * q + 1], v.y, b1);
            }
            float vA = hadd2(add2(a0, a1));
            float vB = hadd2(add2(b0, b1));
            float* orow = og + (size_t)(tile * PTILE + r) * G1;
            orow[gA] = vA;
            orow[gB] = vB;
        }
    }
}

// ============================================================================
// Kernel 2: recurrence. 1 warp per batch element; gates via coalesced LDG
// ring (1 LDG.32/step). slab: [0..7]=h1, [8..15]=x2, [16..21]=h2.
// ============================================================================
template <int RD>
__device__ __forceinline__ void rec_step(
    float en, int lane, float gval,
    float (*shs)[24],
    const u64* __restrict__ w1p, const u64* __restrict__ wi2p,
    const u64* __restrict__ wh2p, u64 bias2p,
    float cn1, float ca1, float cn2, float ca2,
    float& c1, float& c2)
{
    constexpr int WR = RD ^ 1;

    const ulonglong2* hp = reinterpret_cast<const ulonglong2*>(&shs[RD][0]);
    ulonglong2 h01 = hp[0], h23 = hp[1];   // h1[0..7]
    ulonglong2 x01 = hp[2], x23 = hp[3];   // x2[0..7]
    ulonglong2 h2a = hp[4];                // h2[0..3]
    u64        h2b = reinterpret_cast<const u64*>(&shs[RD][0])[10];  // h2[4..5]

    // layer1: g1 = gval + h1 . w1
    u64 C = mul2(h01.x, w1p[0]);
    C = fma2(h01.y, w1p[1], C);
    u64 D = mul2(h23.x, w1p[2]);
    D = fma2(h23.y, w1p[3], D);
    float g1 = gval + hadd2(add2(C, D));

    // layer2: g2 = bias2 + x2 . wi2 + h2 . wh2
    u64 P = fma2(x01.x, wi2p[0], bias2p);
    u64 Q = mul2(x01.y, wi2p[1]);
    P = fma2(x23.x, wi2p[2], P);
    Q = fma2(x23.y, wi2p[3], Q);
    P = fma2(h2a.x, wh2p[0], P);
    Q = fma2(h2a.y, wh2p[1], Q);
    P = fma2(h2b,   wh2p[2], P);
    float g2 = hadd2(add2(P, Q));

    float a1 = fmaf(cn1, tanha(g1), ca1);
    float a2 = fmaf(cn2, tanha(g2), ca2);

    float f1 = shflf(a1, lane + 8);
    float i1 = shflf(a1, lane + 16);
    float o1 = shflf(a1, lane + 24);
    float f2 = shflf(a2, lane + 6);
    float i2 = shflf(a2, lane + 12);
    float o2 = shflf(a2, lane + 18);

    c1 = fmaf(f1, c1, a1 * i1);
    float h1v = o1 * tanha(c1);
    float x2v = tanha(h1v);

    c2 = en * fmaf(f2, c2, a2 * i2);
    float h2v = o2 * tanha(c2);

    if (lane < H1) {
        shs[WR][lane]     = h1v;
        shs[WR][8 + lane] = x2v;
    }
    if (lane < H2) shs[WR][16 + lane] = h2v;
    __syncwarp();
}

__global__ void __launch_bounds__(32)
rec_kernel(const float* __restrict__ W_hh1,
           const float* __restrict__ W_ih2,
           const float* __restrict__ W_hh2,
           const float* __restrict__ b_ih2,
           const float* __restrict__ b_hh2,
           const float* __restrict__ W_fc,
           const float* __restrict__ b_fc,
           float* __restrict__ out) {
    __shared__ __align__(16) float shs[2][24];
    int lane = threadIdx.x;
    int b    = blockIdx.x;

    bool t1 = ((lane >> 3) == 2);
    float cm1 = t1 ? 1.f : 0.5f, cn1 = t1 ? 1.f : 0.5f, ca1 = t1 ? 0.f : 0.5f;
    bool t2 = (lane >= 12 && lane < 18);
    float cm2 = t2 ? 1.f : 0.5f, cn2 = t2 ? 1.f : 0.5f, ca2 = t2 ? 0.f : 0.5f;

    // hidden-recurrence weights, pair-packed along input dim, cm-scaled
    u64 w1p[H1 / 2];
#pragma unroll
    for (int j = 0; j < H1 / 2; j++)
        w1p[j] = pack2(cm1 * W_hh1[lane * H1 + 2 * j], cm1 * W_hh1[lane * H1 + 2 * j + 1]);

    u64 wi2p[H1 / 2], wh2p[H2 / 2], bias2p = 0ull;
#pragma unroll
    for (int j = 0; j < H1 / 2; j++) wi2p[j] = 0ull;
#pragma unroll
    for (int j = 0; j < H2 / 2; j++) wh2p[j] = 0ull;
    if (lane < G2) {
#pragma unroll
        for (int j = 0; j < H1 / 2; j++)
            wi2p[j] = pack2(cm2 * W_ih2[lane * H1 + 2 * j], cm2 * W_ih2[lane * H1 + 2 * j + 1]);
#pragma unroll
        for (int j = 0; j < H2 / 2; j++)
            wh2p[j] = pack2(cm2 * W_hh2[lane * H2 + 2 * j], cm2 * W_hh2[lane * H2 + 2 * j + 1]);
        bias2p = pack2(cm2 * (b_ih2[lane] + b_hh2[lane]), 0.f);
    }

    if (lane < 24) shs[1][lane] = 0.f;
    __syncwarp();

    const float* gp = g_xg + (size_t)b * T_STEPS * G1 + lane;
    float r0 = gp[0], r1 = gp[G1], r2 = gp[2 * G1], r3 = gp[3 * G1];
    float c1 = 0.f, c2 = 0.f;

#pragma unroll 1
    for (int ii = 0; ii < T_STEPS; ii += 4) {
        // prefetch next quad (clamped; batched for MLP=4)
        int tb = (ii + 4 < T_STEPS) ? (ii + 4) : (T_STEPS - 4);
        const float* np = gp + (size_t)tb * G1;
        float n0 = np[0], n1 = np[G1], n2 = np[2 * G1], n3 = np[3 * G1];

        float en0 = (ii == 0) ? 0.f : 1.f;
        rec_step<1>(en0, lane, r0, shs, w1p, wi2p, wh2p, bias2p,
                    cn1, ca1, cn2, ca2, c1, c2);
        rec_step<0>(1.f, lane, r1, shs, w1p, wi2p, wh2p, bias2p,
                    cn1, ca1, cn2, ca2, c1, c2);
        rec_step<1>(1.f, lane, r2, shs, w1p, wi2p, wh2p, bias2p,
                    cn1, ca1, cn2, ca2, c1, c2);
        rec_step<0>(1.f, lane, r3, shs, w1p, wi2p, wh2p, bias2p,
                    cn1, ca1, cn2, ca2, c1, c2);
        r0 = n0; r1 = n1; r2 = n2; r3 = n3;
    }

    // ---- epilogue: layer2(999) from slab[1] (x2(999), h2(998)) ----
    {
        const ulonglong2* hp = reinterpret_cast<const ulonglong2*>(&shs[1][0]);
        ulonglong2 x01 = hp[2], x23 = hp[3], h2a = hp[4];
        u64        h2b = reinterpret_cast<const u64*>(&shs[1][0])[10];

        u64 P = fma2(x01.x, wi2p[0], bias2p);
        u64 Q = mul2(x01.y, wi2p[1]);
        P = fma2(x23.x, wi2p[2], P);
        Q = fma2(x23.y, wi2p[3], Q);
        P = fma2(h2a.x, wh2p[0], P);
        Q = fma2(h2a.y, wh2p[1], Q);
        P = fma2(h2b,   wh2p[2], P);
        float g2 = hadd2(add2(P, Q));

        float a2 = fmaf(cn2, tanha(g2), ca2);
        float f2 = shflf(a2, lane + 6);
        float i2 = shflf(a2, lane + 12);
        float o2 = shflf(a2, lane + 18);
        c2 = fmaf(f2, c2, a2 * i2);
        float tx = tanha(o2 * tanha(c2));   // tanh(h2(999)), valid lanes 0..5

        float s = b_fc[0];
#pragma unroll
        for (int j = 0; j < H2; j++)
            s = fmaf(shflf(tx, j), W_fc[j], s);
        if (lane == 0)
            out[b] = fmaf(0.5f, tanha(0.5f * s), 0.5f);
    }
}

// ============================================================================
extern "C" void kernel_launch(void* const* d_in, const int* in_sizes, int n_in,
                              void* d_out, int out_size) {
    const float* x     = (const float*)d_in[0];
    const float* W_ih1 = (const float*)d_in[1];
    const float* W_hh1 = (const float*)d_in[2];
    const float* b_ih1 = (const float*)d_in[3];
    const float* b_hh1 = (const float*)d_in[4];
    const float* W_ih2 = (const float*)d_in[5];
    const float* W_hh2 = (const float*)d_in[6];
    const float* b_ih2 = (const float*)d_in[7];
    const float* b_hh2 = (const float*)d_in[8];
    const float* W_fc  = (const float*)d_in[9];
    const float* b_fc  = (const float*)d_in[10];
    float* out = (float*)d_out;

    proj_kernel<<<2 * BATCH, PBLK>>>(x, W_ih1, b_ih1, b_hh1);
    rec_kernel<<<BATCH, 32>>>(W_hh1, W_ih2, W_hh2, b_ih2, b_hh2, W_fc, b_fc, out);
}

// round 7
// speedup vs baseline: 1.1458x; 1.1458x over previous
#include <cuda_runtime.h>
#include <cstdint>

#define T_STEPS 1000
#define BATCH   2048
#define FEAT    40
#define H1      8
#define H2      6
#define G1      32
#define G2      24

#define CT      10
#define NCHUNK  (T_STEPS / CT)      // 100
#define SITES   (CT * FEAT / 4)     // 100 float4 per chunk

typedef unsigned long long u64;

// ---------------- f32x2 helpers ----------------
__device__ __forceinline__ u64 pack2(float x, float y) {
    u64 r; asm("mov.b64 %0, {%1, %2};" : "=l"(r) : "f"(x), "f"(y)); return r;
}
__device__ __forceinline__ void unpack2(u64 v, float& x, float& y) {
    asm("mov.b64 {%0, %1}, %2;" : "=f"(x), "=f"(y) : "l"(v));
}
__device__ __forceinline__ u64 fma2(u64 a, u64 b, u64 c) {
    u64 d; asm("fma.rn.f32x2 %0, %1, %2, %3;" : "=l"(d) : "l"(a), "l"(b), "l"(c)); return d;
}
__device__ __forceinline__ u64 mul2(u64 a, u64 b) {
    u64 d; asm("mul.rn.f32x2 %0, %1, %2;" : "=l"(d) : "l"(a), "l"(b)); return d;
}
__device__ __forceinline__ u64 add2(u64 a, u64 b) {
    u64 d; asm("add.rn.f32x2 %0, %1, %2;" : "=l"(d) : "l"(a), "l"(b)); return d;
}
__device__ __forceinline__ u64 scale2(u64 v, float s) {
    float a, b; unpack2(v, a, b); return pack2(a * s, b * s);
}
__device__ __forceinline__ float hadd2(u64 v) {
    float a, b; unpack2(v, a, b); return a + b;
}
__device__ __forceinline__ float tanha(float x) {
    float r; asm("tanh.approx.f32 %0, %1;" : "=f"(r) : "f"(x)); return r;
}
__device__ __forceinline__ float shflf(float v, int src) {
    return __shfl_sync(0xffffffffu, v, src & 31);
}
#define BAR64() asm volatile("bar.sync 0, 64;" ::: "memory")

// ============================================================================
// consumer step: layer1(i) + layer2(i-1). slab: [0..7]=h1, [8..15]=x2, [16..21]=h2
// ============================================================================
template <int RD>
__device__ __forceinline__ void rec_step(
    float en, int lane, float gval,
    float (*shs)[24],
    const u64* __restrict__ w1p, const u64* __restrict__ wi2p,
    const u64* __restrict__ wh2p, u64 bias2p,
    float cn1, float ca1, float cn2, float ca2,
    float& c1, float& c2)
{
    constexpr int WR = RD ^ 1;

    const ulonglong2* hp = reinterpret_cast<const ulonglong2*>(&shs[RD][0]);
    ulonglong2 h01 = hp[0], h23 = hp[1];   // h1[0..7]
    ulonglong2 x01 = hp[2], x23 = hp[3];   // x2[0..7]
    ulonglong2 h2a = hp[4];                // h2[0..3]
    u64        h2b = reinterpret_cast<const u64*>(&shs[RD][0])[10];  // h2[4..5]

    // layer1: g1 = gval + h1 . w1
    u64 C = mul2(h01.x, w1p[0]);
    C = fma2(h01.y, w1p[1], C);
    u64 D = mul2(h23.x, w1p[2]);
    D = fma2(h23.y, w1p[3], D);
    float g1 = gval + hadd2(add2(C, D));

    // layer2: g2 = bias2 + x2 . wi2 + h2 . wh2
    u64 P = fma2(x01.x, wi2p[0], bias2p);
    u64 Q = mul2(x01.y, wi2p[1]);
    P = fma2(x23.x, wi2p[2], P);
    Q = fma2(x23.y, wi2p[3], Q);
    P = fma2(h2a.x, wh2p[0], P);
    Q = fma2(h2a.y, wh2p[1], Q);
    P = fma2(h2b,   wh2p[2], P);
    float g2 = hadd2(add2(P, Q));

    float a1 = fmaf(cn1, tanha(g1), ca1);
    float a2 = fmaf(cn2, tanha(g2), ca2);

    float f1 = shflf(a1, lane + 8);
    float i1 = shflf(a1, lane + 16);
    float o1 = shflf(a1, lane + 24);
    float f2 = shflf(a2, lane + 6);
    float i2 = shflf(a2, lane + 12);
    float o2 = shflf(a2, lane + 18);

    c1 = fmaf(f1, c1, a1 * i1);
    float h1v = o1 * tanha(c1);
    float x2v = tanha(h1v);

    c2 = en * fmaf(f2, c2, a2 * i2);
    float h2v = o2 * tanha(c2);

    if (lane < H1) {
        shs[WR][lane]     = h1v;
        shs[WR][8 + lane] = x2v;
    }
    if (lane < H2) shs[WR][16 + lane] = h2v;
    __syncwarp();
}

// ============================================================================
// fused producer/consumer kernel: 1 block = 1 batch element, 2 warps.
// warp 0: recurrence consumer. warp 1: input-projection producer.
// ============================================================================
__global__ void __launch_bounds__(64)
fused_pc(const float* __restrict__ x,
         const float* __restrict__ W_ih1,
         const float* __restrict__ W_hh1,
         const float* __restrict__ b_ih1,
         const float* __restrict__ b_hh1,
         const float* __restrict__ W_ih2,
         const float* __restrict__ W_hh2,
         const float* __restrict__ b_ih2,
         const float* __restrict__ b_hh2,
         const float* __restrict__ W_fc,
         const float* __restrict__ b_fc,
         float* __restrict__ out) {
    __shared__ __align__(16) float sgate[2][CT][G1];   // gate ring (pre-scaled)
    __shared__ __align__(16) float sx[CT][FEAT];       // x staging (producer-private)
    __shared__ __align__(16) float shs[2][24];         // hidden slabs

    int tid  = threadIdx.x;
    int lane = tid & 31;
    int wid  = tid >> 5;
    int b    = blockIdx.x;

    if (wid == 1) {
        // ======================= PRODUCER =======================
        int l = lane & 15, h = lane >> 4;
        int gA = l, gB = l + 16;
        float cmA = 0.5f;                     // gates 0..15: sigmoid
        float cmB = (l < 8) ? 1.0f : 0.5f;    // 16..23 tanh, 24..31 sigmoid

        u64 wA[FEAT / 2], wB[FEAT / 2];
        {
            const u64* wra = reinterpret_cast<const u64*>(W_ih1 + gA * FEAT);
            const u64* wrb = reinterpret_cast<const u64*>(W_ih1 + gB * FEAT);
#pragma unroll
            for (int p = 0; p < FEAT / 2; p++) {
                wA[p] = scale2(wra[p], cmA);
                wB[p] = scale2(wrb[p], cmB);
            }
        }
        float bA = cmA * (b_ih1[gA] + b_hh1[gA]);
        float bB = cmB * (b_ih1[gB] + b_hh1[gB]);

        const float4* xb = reinterpret_cast<const float4*>(x + (size_t)b * T_STEPS * FEAT);

        // chunk 0 into sgate[0]
        {
            float4 f4[4];
#pragma unroll
            for (int i = 0; i < 4; i++) {
                int s = lane + 32 * i;
                if (s < SITES) f4[i] = xb[s];
            }
#pragma unroll
            for (int i = 0; i < 4; i++) {
                int s = lane + 32 * i;
                if (s < SITES) reinterpret_cast<float4*>(&sx[0][0])[s] = f4[i];
            }
            __syncwarp();
#pragma unroll
            for (int p = 0; p < 5; p++) {
                int r = 2 * p + h;
                const ulonglong2* xr = reinterpret_cast<const ulonglong2*>(&sx[r][0]);
                u64 a0 = pack2(bA, 0.f), a1 = 0ull;
                u64 b0 = pack2(bB, 0.f), b1 = 0ull;
#pragma unroll
                for (int q = 0; q < FEAT / 4; q++) {
                    ulonglong2 v = xr[q];
                    a0 = fma2(wA[2 * q],     v.x, a0);
                    a1 = fma2(wA[2 * q + 1], v.y, a1);
                    b0 = fma2(wB[2 * q],     v.x, b0);
                    b1 = fma2(wB[2 * q + 1], v.y, b1);
                }
                sgate[0][r][gA] = hadd2(add2(a0, a1));
                sgate[0][r][gB] = hadd2(add2(b0, b1));
            }
        }
        BAR64();    // bar_0

#pragma unroll 1
        for (int c = 0; c < NCHUNK; c++) {
            if (c + 1 < NCHUNK) {
                __syncwarp();   // prior chunk's sx reads complete warp-wide
                float4 f4[4];
#pragma unroll
                for (int i = 0; i < 4; i++) {
                    int s = lane + 32 * i;
                    if (s < SITES) f4[i] = xb[(c + 1) * SITES + s];
                }
#pragma unroll
                for (int i = 0; i < 4; i++) {
                    int s = lane + 32 * i;
                    if (s < SITES) reinterpret_cast<float4*>(&sx[0][0])[s] = f4[i];
                }
                __syncwarp();

                float (*dst)[G1] = sgate[(c + 1) & 1];
#pragma unroll
                for (int p = 0; p < 5; p++) {
                    int r = 2 * p + h;
                    const ulonglong2* xr = reinterpret_cast<const ulonglong2*>(&sx[r][0]);
                    u64 a0 = pack2(bA, 0.f), a1 = 0ull;
                    u64 b0 = pack2(bB, 0.f), b1 = 0ull;
#pragma unroll
                    for (int q = 0; q < FEAT / 4; q++) {
                        ulonglong2 v = xr[q];
                        a0 = fma2(wA[2 * q],     v.x, a0);
                        a1 = fma2(wA[2 * q + 1], v.y, a1);
                        b0 = fma2(wB[2 * q],     v.x, b0);
                        b1 = fma2(wB[2 * q + 1], v.y, b1);
                    }
                    dst[r][gA] = hadd2(add2(a0, a1));
                    dst[r][gB] = hadd2(add2(b0, b1));
                }
            }
            BAR64();
        }
        // producer done
    } else {
        // ======================= CONSUMER =======================
        bool t1 = ((lane >> 3) == 2);
        float cm1 = t1 ? 1.f : 0.5f, cn1 = t1 ? 1.f : 0.5f, ca1 = t1 ? 0.f : 0.5f;
        bool t2 = (lane >= 12 && lane < 18);
        float cm2 = t2 ? 1.f : 0.5f, cn2 = t2 ? 1.f : 0.5f, ca2 = t2 ? 0.f : 0.5f;

        u64 w1p[H1 / 2];
#pragma unroll
        for (int j = 0; j < H1 / 2; j++)
            w1p[j] = pack2(cm1 * W_hh1[lane * H1 + 2 * j], cm1 * W_hh1[lane * H1 + 2 * j + 1]);

        u64 wi2p[H1 / 2], wh2p[H2 / 2], bias2p = 0ull;
#pragma unroll
        for (int j = 0; j < H1 / 2; j++) wi2p[j] = 0ull;
#pragma unroll
        for (int j = 0; j < H2 / 2; j++) wh2p[j] = 0ull;
        if (lane < G2) {
#pragma unroll
            for (int j = 0; j < H1 / 2; j++)
                wi2p[j] = pack2(cm2 * W_ih2[lane * H1 + 2 * j], cm2 * W_ih2[lane * H1 + 2 * j + 1]);
#pragma unroll
            for (int j = 0; j < H2 / 2; j++)
                wh2p[j] = pack2(cm2 * W_hh2[lane * H2 + 2 * j], cm2 * W_hh2[lane * H2 + 2 * j + 1]);
            bias2p = pack2(cm2 * (b_ih2[lane] + b_hh2[lane]), 0.f);
        }

        if (lane < 24) shs[1][lane] = 0.f;
        float c1 = 0.f, c2 = 0.f;
        BAR64();    // bar_0

#pragma unroll 1
        for (int c = 0; c < NCHUNK; c++) {
            const float* gr = &sgate[c & 1][0][0];
            float en0 = (c == 0) ? 0.f : 1.f;

            rec_step<1>(en0, lane, gr[0 * G1 + lane], shs, w1p, wi2p, wh2p, bias2p,
                        cn1, ca1, cn2, ca2, c1, c2);
            rec_step<0>(1.f, lane, gr[1 * G1 + lane], shs, w1p, wi2p, wh2p, bias2p,
                        cn1, ca1, cn2, ca2, c1, c2);
            rec_step<1>(1.f, lane, gr[2 * G1 + lane], shs, w1p, wi2p, wh2p, bias2p,
                        cn1, ca1, cn2, ca2, c1, c2);
            rec_step<0>(1.f, lane, gr[3 * G1 + lane], shs, w1p, wi2p, wh2p, bias2p,
                        cn1, ca1, cn2, ca2, c1, c2);
            rec_step<1>(1.f, lane, gr[4 * G1 + lane], shs, w1p, wi2p, wh2p, bias2p,
                        cn1, ca1, cn2, ca2, c1, c2);
            rec_step<0>(1.f, lane, gr[5 * G1 + lane], shs, w1p, wi2p, wh2p, bias2p,
                        cn1, ca1, cn2, ca2, c1, c2);
            rec_step<1>(1.f, lane, gr[6 * G1 + lane], shs, w1p, wi2p, wh2p, bias2p,
                        cn1, ca1, cn2, ca2, c1, c2);
            rec_step<0>(1.f, lane, gr[7 * G1 + lane], shs, w1p, wi2p, wh2p, bias2p,
                        cn1, ca1, cn2, ca2, c1, c2);
            rec_step<1>(1.f, lane, gr[8 * G1 + lane], shs, w1p, wi2p, wh2p, bias2p,
                        cn1, ca1, cn2, ca2, c1, c2);
            rec_step<0>(1.f, lane, gr[9 * G1 + lane], shs, w1p, wi2p, wh2p, bias2p,
                        cn1, ca1, cn2, ca2, c1, c2);
            BAR64();
        }

        // ---- epilogue: layer2(999) from slab[1] (x2(999), h2(998)) ----
        const ulonglong2* hp = reinterpret_cast<const ulonglong2*>(&shs[1][0]);
        ulonglong2 x01 = hp[2], x23 = hp[3], h2a = hp[4];
        u64        h2b = reinterpret_cast<const u64*>(&shs[1][0])[10];

        u64 P = fma2(x01.x, wi2p[0], bias2p);
        u64 Q = mul2(x01.y, wi2p[1]);
        P = fma2(x23.x, wi2p[2], P);
        Q = fma2(x23.y, wi2p[3], Q);
        P = fma2(h2a.x, wh2p[0], P);
        Q = fma2(h2a.y, wh2p[1], Q);
        P = fma2(h2b,   wh2p[2], P);
        float g2 = hadd2(add2(P, Q));

        float a2 = fmaf(cn2, tanha(g2), ca2);
        float f2 = shflf(a2, lane + 6);
        float i2 = shflf(a2, lane + 12);
        float o2 = shflf(a2, lane + 18);
        c2 = fmaf(f2, c2, a2 * i2);
        float tx = tanha(o2 * tanha(c2));   // tanh(h2(999)), valid lanes 0..5

        float s = b_fc[0];
#pragma unroll
        for (int j = 0; j < H2; j++)
            s = fmaf(shflf(tx, j), W_fc[j], s);
        if (lane == 0)
            out[b] = fmaf(0.5f, tanha(0.5f * s), 0.5f);
    }
}

// ============================================================================
extern "C" void kernel_launch(void* const* d_in, const int* in_sizes, int n_in,
                              void* d_out, int out_size) {
    const float* x     = (const float*)d_in[0];
    const float* W_ih1 = (const float*)d_in[1];
    const float* W_hh1 = (const float*)d_in[2];
    const float* b_ih1 = (const float*)d_in[3];
    const float* b_hh1 = (const float*)d_in[4];
    const float* W_ih2 = (const float*)d_in[5];
    const float* W_hh2 = (const float*)d_in[6];
    const float* b_ih2 = (const float*)d_in[7];
    const float* b_hh2 = (const float*)d_in[8];
    const float* W_fc  = (const float*)d_in[9];
    const float* b_fc  = (const float*)d_in[10];
    float* out = (float*)d_out;

    fused_pc<<<BATCH, 64>>>(x, W_ih1, W_hh1, b_ih1, b_hh1,
                            W_ih2, W_hh2, b_ih2, b_hh2, W_fc, b_fc, out);
}